// round 3
// baseline (speedup 1.0000x reference)
#include <cuda_runtime.h>
#include <cuda_bf16.h>
#include <cstdint>

#define HID 20
#define NMID 8
#define BLK 128

typedef unsigned long long ull;

__device__ __forceinline__ ull pk(float lo, float hi) {
    ull r;
    asm("mov.b64 %0, {%1, %2};" : "=l"(r) : "f"(lo), "f"(hi));
    return r;
}
__device__ __forceinline__ void upk(ull v, float& lo, float& hi) {
    asm("mov.b64 {%0, %1}, %2;" : "=f"(lo), "=f"(hi) : "l"(v));
}
__device__ __forceinline__ ull ffma2(ull a, ull b, ull c) {
    ull d;
    asm("fma.rn.f32x2 %0, %1, %2, %3;" : "=l"(d) : "l"(a), "l"(b), "l"(c));
    return d;
}
__device__ __forceinline__ ull fadd2(ull a, ull b) {
    ull d;
    asm("add.rn.f32x2 %0, %1, %2;" : "=l"(d) : "l"(a), "l"(b));
    return d;
}

// fast tanh: t = 1 - 2/(exp(2z)+1). Saturates cleanly (exp -> 0 or inf).
__device__ __forceinline__ float tanh_fast(float z) {
    float e = __expf(2.0f * z);
    return 1.0f - __fdividef(2.0f, e + 1.0f);
}

__global__ void __launch_bounds__(BLK, 2)
pde_mlp_kernel(const float* __restrict__ x,
               const float* __restrict__ W_in,
               const float* __restrict__ b_in,
               const float* __restrict__ W_mid,
               const float* __restrict__ b_mid,
               const float* __restrict__ W_out,
               const float* __restrict__ b_out,
               float* __restrict__ out,
               float* __restrict__ pde,
               int n)
{
    // Static shared: 20480 + 25600 + 640 + 160 + 80 + 160 + 8 = 47128 B < 48 KB
    __shared__ __align__(16) ull  sQst[HID * BLK];        // Q staging, per-thread column
    __shared__ __align__(16) ull  sW[NMID * HID * HID];   // mid weights, dup (w,w)
    __shared__ float sB[NMID * HID];
    __shared__ float sWin[HID * 2];
    __shared__ float sbin[HID];
    __shared__ __align__(16) ull  sWo[HID];
    __shared__ float sbo;

    const int tid = threadIdx.x;
    for (int idx = tid; idx < NMID * HID * HID; idx += BLK) {
        float w = W_mid[idx];
        sW[idx] = pk(w, w);
    }
    for (int idx = tid; idx < NMID * HID; idx += BLK)
        sB[idx] = b_mid[idx];
    if (tid < HID * 2) sWin[tid] = W_in[tid];
    if (tid < HID) {
        sbin[tid] = b_in[tid];
        float wo = W_out[tid];
        sWo[tid] = pk(wo, wo);
    }
    if (tid == 0) sbo = b_out[0];
    __syncthreads();

    const int i = blockIdx.x * BLK + tid;
    if (i >= n) return;

    const float2 xi = reinterpret_cast<const float2*>(x)[i];
    const float xt = xi.x;   // x0 = t
    const float xx = xi.y;   // x1 = x

    // State: P[k] = (h_k, v_k)   v = dh/dx1
    //        Q[k] = (u_k, w_k)   u = dh/dx0 , w = d2h/dx1^2
    ull P[HID], Q[HID];

    // ---- input layer ----
#pragma unroll
    for (int j = 0; j < HID; j++) {
        float w0 = sWin[2 * j];
        float w1 = sWin[2 * j + 1];
        float z  = fmaf(w0, xt, fmaf(w1, xx, sbin[j]));
        float t  = tanh_fast(z);
        float dt = fmaf(-t, t, 1.0f);
        float v  = dt * w1;
        P[j] = pk(t, v);
        Q[j] = pk(dt * w0, -2.0f * t * v * w1);   // w' = -2 t dt w1^2
    }

    // ---- 8 mid layers ----
    // New P goes to registers (nP); new Q staged in the thread-private smem
    // column (program-ordered within a thread, no __syncthreads needed),
    // reloaded after the row loop. Keeps peak live regs ~190 -> no spills.
    ull* myQ = &sQst[tid];
    for (int l = 0; l < NMID; l++) {
        const ull*   sWl = &sW[l * HID * HID];
        const float* sBl = &sB[l * HID];
        ull nP[HID];
#pragma unroll
        for (int j = 0; j < HID; j++) {
            ull aP0 = pk(sBl[j], 0.0f);  // bias enters primal only
            ull aP1 = 0ull, aQ0 = 0ull, aQ1 = 0ull;
            const ull* wrow = &sWl[j * HID];
#pragma unroll
            for (int k = 0; k < HID; k += 4) {
                ulonglong2 wa = *reinterpret_cast<const ulonglong2*>(&wrow[k]);
                ulonglong2 wb = *reinterpret_cast<const ulonglong2*>(&wrow[k + 2]);
                aP0 = ffma2(wa.x, P[k],     aP0);
                aQ0 = ffma2(wa.x, Q[k],     aQ0);
                aP0 = ffma2(wa.y, P[k + 1], aP0);
                aQ0 = ffma2(wa.y, Q[k + 1], aQ0);
                aP1 = ffma2(wb.x, P[k + 2], aP1);
                aQ1 = ffma2(wb.x, Q[k + 2], aQ1);
                aP1 = ffma2(wb.y, P[k + 3], aP1);
                aQ1 = ffma2(wb.y, Q[k + 3], aQ1);
            }
            ull accP = fadd2(aP0, aP1);
            ull accQ = fadd2(aQ0, aQ1);
            float z, zv, zu, zw;
            upk(accP, z, zv);
            upk(accQ, zu, zw);
            float t  = tanh_fast(z);
            float dt = fmaf(-t, t, 1.0f);
            float vn = dt * zv;
            nP[j] = pk(t, vn);
            // w' = dt*zw - 2*t*dt*zv^2 = dt*zw - 2*t*vn*zv
            myQ[j * BLK] = pk(dt * zu, fmaf(dt, zw, -2.0f * t * vn * zv));
        }
#pragma unroll
        for (int j = 0; j < HID; j++) {
            P[j] = nP[j];
            Q[j] = myQ[j * BLK];
        }
    }

    // ---- output layer (linear) ----
    ull aP = 0ull, aQ = 0ull;
#pragma unroll
    for (int j = 0; j < HID; j++) {
        aP = ffma2(sWo[j], P[j], aP);
        aQ = ffma2(sWo[j], Q[j], aQ);
    }
    float f, fv, fu, fw;
    upk(aP, f, fv);
    upk(aQ, fu, fw);
    f += sbo;

    // pde = 0.5*x^2 + f_t + 0.5*f_xx + 0.5*x*f_x - (C^2/(4 C_F)) * f_x^2
    // C^2/(4*C_F) = 0.25/3.6 = 0.0694444...
    float p = fmaf(0.5f * xx, xx, fu);
    p = fmaf(0.5f, fw, p);
    p = fmaf(0.5f * xx, fv, p);
    p = fmaf(-0.06944444444444445f * fv, fv, p);

    out[i] = f;
    pde[i] = p;
}

extern "C" void kernel_launch(void* const* d_in, const int* in_sizes, int n_in,
                              void* d_out, int out_size) {
    const float* x     = (const float*)d_in[0];
    const float* W_in  = (const float*)d_in[1];
    const float* b_in  = (const float*)d_in[2];
    const float* W_mid = (const float*)d_in[3];
    const float* b_mid = (const float*)d_in[4];
    const float* W_out = (const float*)d_in[5];
    const float* b_out = (const float*)d_in[6];

    const int n = in_sizes[0] / 2;            // x is (N, 2)
    float* out = (float*)d_out;               // first N: f
    float* pde = out + n;                     // next N: pde residual

    const int grid = (n + BLK - 1) / BLK;
    pde_mlp_kernel<<<grid, BLK>>>(x, W_in, b_in, W_mid, b_mid,
                                  W_out, b_out, out, pde, n);
}

// round 17
// speedup vs baseline: 1.2556x; 1.2556x over previous
#include <cuda_runtime.h>
#include <cuda_bf16.h>
#include <cstdint>

#define HID 20
#define NMID 8
#define BLK 128
#define NP 10            // HID/2 pairs

typedef unsigned long long ull;

__device__ __forceinline__ ull pk(float lo, float hi) {
    ull r;
    asm("mov.b64 %0, {%1, %2};" : "=l"(r) : "f"(lo), "f"(hi));
    return r;
}
__device__ __forceinline__ void upk(ull v, float& lo, float& hi) {
    asm("mov.b64 {%0, %1}, %2;" : "=f"(lo), "=f"(hi) : "l"(v));
}
__device__ __forceinline__ ull ffma2(ull a, ull b, ull c) {
    ull d;
    asm("fma.rn.f32x2 %0, %1, %2, %3;" : "=l"(d) : "l"(a), "l"(b), "l"(c));
    return d;
}
__device__ __forceinline__ float hadd(ull a) {
    float lo, hi; upk(a, lo, hi); return lo + hi;
}

// fast tanh: t = 1 - 2/(exp(2z)+1). Saturates cleanly (exp -> 0 or inf).
__device__ __forceinline__ float tanh_fast(float z) {
    float e = __expf(2.0f * z);
    return 1.0f - __fdividef(2.0f, e + 1.0f);
}

__global__ void __launch_bounds__(BLK)
pde_mlp_kernel(const float* __restrict__ x,
               const float* __restrict__ W_in,
               const float* __restrict__ b_in,
               const float* __restrict__ W_mid,
               const float* __restrict__ b_mid,
               const float* __restrict__ W_out,
               const float* __restrict__ b_out,
               float* __restrict__ out,
               float* __restrict__ pde,
               int n)
{
    // Weights as NATURAL k-adjacent float2 pairs (no duplication): 12.8 KB.
    __shared__ __align__(16) ull  sW[NMID * HID * NP];   // 1600 ull
    __shared__ float sB[NMID * HID];
    __shared__ float sWin[HID * 2];
    __shared__ float sbin[HID];
    __shared__ __align__(16) ull  sWo[NP];
    __shared__ float sbo;

    const int tid = threadIdx.x;
    // raw copy: W_mid rows are 20 contiguous floats = 10 natural pairs
    const ull* Wm64 = reinterpret_cast<const ull*>(W_mid);
    for (int idx = tid; idx < NMID * HID * NP; idx += BLK)
        sW[idx] = Wm64[idx];
    for (int idx = tid; idx < NMID * HID; idx += BLK)
        sB[idx] = b_mid[idx];
    if (tid < HID * 2) sWin[tid] = W_in[tid];
    if (tid < HID)     sbin[tid] = b_in[tid];
    if (tid < NP)      sWo[tid]  = reinterpret_cast<const ull*>(W_out)[tid];
    if (tid == 0)      sbo = b_out[0];
    __syncthreads();

    const int i = blockIdx.x * BLK + tid;
    if (i >= n) return;

    const float2 xi = reinterpret_cast<const float2*>(x)[i];
    const float xt = xi.x;   // x0 = t
    const float xx = xi.y;   // x1 = x

    // k-paired state: element pair p holds neurons (2p, 2p+1)
    //   h: primal, v: dh/dx1, u: dh/dx0, w: d2h/dx1^2
    ull h[NP], v[NP], u[NP], w[NP];

    // ---- input layer ----
#pragma unroll
    for (int p = 0; p < NP; p++) {
        float t_[2], v_[2], u_[2], w_[2];
#pragma unroll
        for (int r = 0; r < 2; r++) {
            int j = 2 * p + r;
            float w0 = sWin[2 * j];
            float w1 = sWin[2 * j + 1];
            float z  = fmaf(w0, xt, fmaf(w1, xx, sbin[j]));
            float t  = tanh_fast(z);
            float dt = fmaf(-t, t, 1.0f);
            t_[r] = t;
            v_[r] = dt * w1;
            u_[r] = dt * w0;
            w_[r] = -2.0f * t * v_[r] * w1;   // -2 t dt w1^2
        }
        h[p] = pk(t_[0], t_[1]);
        v[p] = pk(v_[0], v_[1]);
        u[p] = pk(u_[0], u_[1]);
        w[p] = pk(w_[0], w_[1]);
    }

    // ---- 8 mid layers, two rows per iteration (8 independent FMA chains) ----
    for (int l = 0; l < NMID; l++) {
        const ull*   Wl = &sW[l * HID * NP];
        const float* Bl = &sB[l * HID];
        ull nh[NP], nv[NP], nu[NP], nw[NP];
#pragma unroll
        for (int p = 0; p < NP; p++) {
            const ull* r0 = &Wl[(2 * p) * NP];
            const ull* r1 = r0 + NP;
            // bias folded into the primal accumulators' initial value
            ull aH0 = pk(Bl[2 * p], 0.0f);
            ull aH1 = pk(Bl[2 * p + 1], 0.0f);
            ull aV0 = 0, aU0 = 0, aW0 = 0;
            ull aV1 = 0, aU1 = 0, aW1 = 0;
#pragma unroll
            for (int k = 0; k < NP; k += 2) {
                ulonglong2 wa = *reinterpret_cast<const ulonglong2*>(&r0[k]);
                ulonglong2 wb = *reinterpret_cast<const ulonglong2*>(&r1[k]);
                aH0 = ffma2(wa.x, h[k],     aH0);
                aV0 = ffma2(wa.x, v[k],     aV0);
                aU0 = ffma2(wa.x, u[k],     aU0);
                aW0 = ffma2(wa.x, w[k],     aW0);
                aH1 = ffma2(wb.x, h[k],     aH1);
                aV1 = ffma2(wb.x, v[k],     aV1);
                aU1 = ffma2(wb.x, u[k],     aU1);
                aW1 = ffma2(wb.x, w[k],     aW1);
                aH0 = ffma2(wa.y, h[k + 1], aH0);
                aV0 = ffma2(wa.y, v[k + 1], aV0);
                aU0 = ffma2(wa.y, u[k + 1], aU0);
                aW0 = ffma2(wa.y, w[k + 1], aW0);
                aH1 = ffma2(wb.y, h[k + 1], aH1);
                aV1 = ffma2(wb.y, v[k + 1], aV1);
                aU1 = ffma2(wb.y, u[k + 1], aU1);
                aW1 = ffma2(wb.y, w[k + 1], aW1);
            }
            // row 2p
            float z0  = hadd(aH0);
            float zv0 = hadd(aV0);
            float zu0 = hadd(aU0);
            float zw0 = hadd(aW0);
            float t0  = tanh_fast(z0);
            float d0  = fmaf(-t0, t0, 1.0f);
            float vn0 = d0 * zv0;
            float un0 = d0 * zu0;
            float m0  = t0 * vn0;
            float wn0 = fmaf(d0, zw0, -2.0f * m0 * zv0);
            // row 2p+1
            float z1  = hadd(aH1);
            float zv1 = hadd(aV1);
            float zu1 = hadd(aU1);
            float zw1 = hadd(aW1);
            float t1  = tanh_fast(z1);
            float d1  = fmaf(-t1, t1, 1.0f);
            float vn1 = d1 * zv1;
            float un1 = d1 * zu1;
            float m1  = t1 * vn1;
            float wn1 = fmaf(d1, zw1, -2.0f * m1 * zv1);

            nh[p] = pk(t0,  t1);
            nv[p] = pk(vn0, vn1);
            nu[p] = pk(un0, un1);
            nw[p] = pk(wn0, wn1);
        }
#pragma unroll
        for (int p = 0; p < NP; p++) {
            h[p] = nh[p]; v[p] = nv[p]; u[p] = nu[p]; w[p] = nw[p];
        }
    }

    // ---- output layer (linear) ----
    ull aF = 0, aV = 0, aU = 0, aW = 0;
#pragma unroll
    for (int p = 0; p < NP; p++) {
        ull wo = sWo[p];
        aF = ffma2(wo, h[p], aF);
        aV = ffma2(wo, v[p], aV);
        aU = ffma2(wo, u[p], aU);
        aW = ffma2(wo, w[p], aW);
    }
    float f  = hadd(aF) + sbo;
    float fv = hadd(aV);
    float fu = hadd(aU);
    float fw = hadd(aW);

    // pde = 0.5*x^2 + f_t + 0.5*f_xx + 0.5*x*f_x - (C^2/(4 C_F)) * f_x^2
    // C^2/(4*C_F) = 0.25/3.6 = 0.0694444...
    float p = fmaf(0.5f * xx, xx, fu);
    p = fmaf(0.5f, fw, p);
    p = fmaf(0.5f * xx, fv, p);
    p = fmaf(-0.06944444444444445f * fv, fv, p);

    out[i] = f;
    pde[i] = p;
}

extern "C" void kernel_launch(void* const* d_in, const int* in_sizes, int n_in,
                              void* d_out, int out_size) {
    const float* x     = (const float*)d_in[0];
    const float* W_in  = (const float*)d_in[1];
    const float* b_in  = (const float*)d_in[2];
    const float* W_mid = (const float*)d_in[3];
    const float* b_mid = (const float*)d_in[4];
    const float* W_out = (const float*)d_in[5];
    const float* b_out = (const float*)d_in[6];

    const int n = in_sizes[0] / 2;            // x is (N, 2)
    float* out = (float*)d_out;               // first N: f
    float* pde = out + n;                     // next N: pde residual

    const int grid = (n + BLK - 1) / BLK;
    pde_mlp_kernel<<<grid, BLK>>>(x, W_in, b_in, W_mid, b_mid,
                                  W_out, b_out, out, pde, n);
}